// round 15
// baseline (speedup 1.0000x reference)
#include <cuda_runtime.h>
#include <stdint.h>
#include <math.h>

#define NBLK 128
#define NTHR 256

// __device__ scratch (allocation-free rule)
__device__ float g_P[128 * 64 * 256];        // P[b,w,e] (8 MB)
__device__ float g_HC[128 * 512];            // [b][0:256]=h, [b][256:512]=c
__device__ float g_Sp[16][128 * 256];        // S kc-partials (K=32 each)
__device__ float g_Gp[4][128 * 1024];        // Ghh kc-partials (K=64 each)
__device__ unsigned g_cntP;
__device__ unsigned g_cntS[2], g_cntG[2], g_cntH[2];  // per-batch-half flags
__device__ unsigned g_bar_gen, g_bar_cnt;             // final barrier only

// ---- smem float offsets (total 55840 floats = 223360 B) ----
#define F_ENC   0        // 16384
#define F_P     16384    // 16384
#define F_W2    32768    // 256
#define F_WIH   33024    // 4096
#define F_BIAS  37120    // 1024 (bih+bhh)
#define F_FCW   38144    // 1048 (fcw 1040, pad)
#define F_YH    39192    // 256  (yh[b] all steps)
#define F_CONST 39448    // 8    ([0]=b2, [4..7]=fcb)
#define F_SCR   39456    // 16384: init Ast|Bst; steady: Ast/overlay | BwS | BwG
#define SMEM_BYTES (55840 * 4)

// steady-state scratch sublayout (floats, relative to F_SCR)
#define SC_AST  0        // 4096 (Ast, K<=64; phase-B overlay lives here too)
#define SC_BWS  4096     // 2048 (persistent S weight tile 64x32)
#define SC_BWG  6144     // 4096 (persistent G weight tile 64x64)

// ---------------------------------------------------------------------------
__device__ __forceinline__ float tanh_fast(float x) {
    float y;
    asm("tanh.approx.f32 %0, %1;" : "=f"(y) : "f"(x));
    return y;
}
__device__ __forceinline__ float sigmoid_fast(float x) {
    return fmaf(tanh_fast(0.5f * x), 0.5f, 0.5f);
}
__device__ __forceinline__ unsigned long long pack2(float x, float y) {
    unsigned long long r;
    asm("mov.b64 %0, {%1, %2};" : "=l"(r) : "f"(x), "f"(y));
    return r;
}
__device__ __forceinline__ unsigned long long fma2(unsigned long long a,
                                                   unsigned long long b,
                                                   unsigned long long c) {
    unsigned long long d;
    asm("fma.rn.f32x2 %0, %1, %2, %3;" : "=l"(d) : "l"(a), "l"(b), "l"(c));
    return d;
}
__device__ __forceinline__ float2 unpack2(unsigned long long v) {
    float lo, hi;
    asm("mov.b64 {%0, %1}, %2;" : "=f"(lo), "=f"(hi) : "l"(v));
    return make_float2(lo, hi);
}

// fire-and-forget arrival (tid0, after __syncthreads)
__device__ __forceinline__ void flag_arrive(unsigned* p) {
    asm volatile("red.release.gpu.global.add.u32 [%0], %1;" :: "l"(p), "r"(1u));
}
__device__ __forceinline__ void flag_poll_ge(unsigned* p, unsigned target) {
    unsigned v;
    do {
        asm volatile("ld.acquire.gpu.global.u32 %0, [%1];" : "=r"(v) : "l"(p));
    } while (v < target);
}
__device__ __forceinline__ void flag_wait_ge(unsigned* p, unsigned target) {
    if (threadIdx.x == 0) flag_poll_ge(p, target);
    __syncthreads();
}

// two-hop barrier, used ONCE after the loop (reset safety)
__device__ __forceinline__ void grid_barrier() {
    __syncthreads();
    if (threadIdx.x == 0) {
        unsigned gen;
        asm volatile("ld.acquire.gpu.global.u32 %0, [%1];" : "=r"(gen) : "l"(&g_bar_gen));
        if (blockIdx.x == 0) {
            unsigned c;
            do {
                asm volatile("ld.acquire.gpu.global.u32 %0, [%1];" : "=r"(c) : "l"(&g_bar_cnt));
            } while (c != NBLK - 1);
            asm volatile("st.relaxed.gpu.global.u32 [%0], %1;" :: "l"(&g_bar_cnt), "r"(0u));
            asm volatile("st.release.gpu.global.u32 [%0], %1;" :: "l"(&g_bar_gen), "r"(gen + 1u));
        } else {
            asm volatile("red.release.gpu.global.add.u32 [%0], %1;" :: "l"(&g_bar_cnt), "r"(1u));
            unsigned g2;
            do {
                asm volatile("ld.acquire.gpu.global.u32 %0, [%1];" : "=r"(g2) : "l"(&g_bar_gen));
            } while (g2 == gen);
        }
    }
    __syncthreads();
}

// ---------------------------------------------------------------------------
// Stage 64 rows x K cols of X (row-major ldx) into Xst[k][r] (stride 64).
__device__ __forceinline__ void stageK(const float* __restrict__ Xp, int ldx,
                                       float* __restrict__ Xst, int K) {
    const int tid = threadIdx.x;
    const int r  = tid & 63;
    const int kg = tid >> 6;
    const int nq = K >> 4;
#pragma unroll
    for (int q = 0; q < nq; q++) {
        int k4 = (kg + q * 4) << 2;
        float4 v = *(const float4*)(Xp + r * ldx + k4);
        Xst[(k4 + 0) * 64 + r] = v.x;
        Xst[(k4 + 1) * 64 + r] = v.y;
        Xst[(k4 + 2) * 64 + r] = v.z;
        Xst[(k4 + 3) * 64 + r] = v.w;
    }
}

// 64x64 x K accumulate with packed f32x2 FMA. acc[4][2] packed pairs.
__device__ __forceinline__ void mmaK(const float* __restrict__ Ast,
                                     const float* __restrict__ Bst,
                                     unsigned long long acc[4][2], int K) {
    const int ty = threadIdx.x >> 4, tx = threadIdx.x & 15;
#pragma unroll 8
    for (int k = 0; k < K; k++) {
        float4 a = *(const float4*)&Ast[k * 64 + ty * 4];
        ulonglong2 b = *(const ulonglong2*)&Bst[k * 64 + tx * 4];
        unsigned long long a0 = pack2(a.x, a.x);
        unsigned long long a1 = pack2(a.y, a.y);
        unsigned long long a2 = pack2(a.z, a.z);
        unsigned long long a3 = pack2(a.w, a.w);
        acc[0][0] = fma2(a0, b.x, acc[0][0]); acc[0][1] = fma2(a0, b.y, acc[0][1]);
        acc[1][0] = fma2(a1, b.x, acc[1][0]); acc[1][1] = fma2(a1, b.y, acc[1][1]);
        acc[2][0] = fma2(a2, b.x, acc[2][0]); acc[2][1] = fma2(a2, b.y, acc[2][1]);
        acc[3][0] = fma2(a3, b.x, acc[3][0]); acc[3][1] = fma2(a3, b.y, acc[3][1]);
    }
}

__device__ __forceinline__ void epilogue(unsigned long long acc[4][2],
                                         float* __restrict__ Cptr, int ldc,
                                         const float* __restrict__ bias) {
    const int ty = threadIdx.x >> 4, tx = threadIdx.x & 15;
    float4 bb = make_float4(0.f, 0.f, 0.f, 0.f);
    if (bias) bb = *(const float4*)&bias[tx * 4];
#pragma unroll
    for (int i = 0; i < 4; i++) {
        float2 lo = unpack2(acc[i][0]);
        float2 hi = unpack2(acc[i][1]);
        float4 o;
        o.x = lo.x + bb.x; o.y = lo.y + bb.y;
        o.z = hi.x + bb.z; o.w = hi.y + bb.w;
        *(float4*)&Cptr[(ty * 4 + i) * ldc + tx * 4] = o;
    }
}

// Full tile GEMM (stages both operands) for the one-time P precompute.
__device__ __forceinline__ void gemm64_full(
    const float* __restrict__ Aptr, int lda,
    const float* __restrict__ Bptr, int ldb,
    float* __restrict__ Cptr, int ldc,
    int nchunk, const float* __restrict__ bias,
    float* __restrict__ Ast, float* __restrict__ Bst)
{
    unsigned long long acc[4][2];
#pragma unroll
    for (int i = 0; i < 4; i++) { acc[i][0] = 0ull; acc[i][1] = 0ull; }
    for (int c = 0; c < nchunk; c++) {
        stageK(Aptr + c * 128, lda, Ast, 128);
        stageK(Bptr + c * 128, ldb, Bst, 128);
        __syncthreads();
        mmaK(Ast, Bst, acc, 128);
        __syncthreads();
    }
    epilogue(acc, Cptr, ldc, bias);
}

// ---------------------------------------------------------------------------
__global__ __launch_bounds__(NTHR, 1)
void decoder_persistent(
    const float* __restrict__ enc,  const float* __restrict__ yh,
    const float* __restrict__ w1,   const float* __restrict__ b1,
    const float* __restrict__ w2,   const float* __restrict__ b2,
    const float* __restrict__ wih,  const float* __restrict__ whh,
    const float* __restrict__ bih,  const float* __restrict__ bhh,
    const float* __restrict__ fcw,  const float* __restrict__ fcb,
    const float* __restrict__ fcfw, const float* __restrict__ fcfb,
    float* __restrict__ out)
{
    extern __shared__ float sm[];
    float* sEnc  = sm + F_ENC;
    float* sP    = sm + F_P;
    float* sW2   = sm + F_W2;
    float* sWih  = sm + F_WIH;
    float* sBias = sm + F_BIAS;
    float* sFcw  = sm + F_FCW;
    float* sYh   = sm + F_YH;
    float* sCst  = sm + F_CONST;
    float* scr   = sm + F_SCR;
    float* Ast   = scr + SC_AST;   // 4096 floats (K<=64)
    float* BwS   = scr + SC_BWS;   // persistent S weight tile (64x32)
    float* BwG   = scr + SC_BWG;   // persistent G weight tile (64x64)
    // phase-B overlay (inside Ast region; BwS/BwG untouched)
    float* sS    = scr;
    float* sCtx  = scr + 256;
    float* sAttn = scr + 576;
    float* sWsum = scr + 640;
    float* sY    = scr + 656;
    float* sH    = scr + 672;      // 672..927
    float* sGG   = scr + 1024;     // 1024..2047 (gate partial sums)

    const int b   = blockIdx.x;
    const int tid = threadIdx.x;
    const int lane = tid & 31, wid = tid >> 5;
    const int bh  = b >> 6;                 // my batch half

    // ---- init: zero h,c for my batch ----
    g_HC[b * 512 + tid]       = 0.f;
    g_HC[b * 512 + 256 + tid] = 0.f;

    // ---- precompute P = enc · W1_e^T + b1 : 512 tiles of 64x64x256 ----
    for (int q = 0; q < 4; q++) {
        int tile = b + NBLK * q;           // mt 0..127, nt 0..3
        int mt = tile >> 2, nt = tile & 3;
        gemm64_full(enc + mt * 64 * 256, 256,
                    w1 + nt * 64 * 768 + 512, 768,
                    g_P + mt * 64 * 256 + nt * 64, 256,
                    2, b1 + nt * 64, scr, scr + 8192);
    }
    __syncthreads();
    if (tid == 0) flag_arrive(&g_cntP);
    flag_wait_ge(&g_cntP, NBLK);

    // ---- decode my two fixed per-step GEMM tasks ----
    // S: b = kc*8 + mt*4 + nt  (kc 0..15, mt 0..1, nt 0..3), K=32
    // G: b = kc*32 + mt*16 + nt (kc 0..3, mt 0..1, nt 0..15), K=64
    const float *sA, *sW, *gA, *gW;
    float *sC, *gC;
    int smt, gmt;
    {
        int kc = b >> 3, mt = (b >> 2) & 1, nt = b & 3;
        smt = mt;
        sA = g_HC + mt * 64 * 512 + kc * 32;
        sW = w1 + nt * 64 * 768 + kc * 32;
        sC = g_Sp[kc] + mt * 64 * 256 + nt * 64;
    }
    {
        int kc = b >> 5, mt = (b >> 4) & 1, nt = b & 15;
        gmt = mt;
        gA = g_HC + mt * 64 * 512 + kc * 64;
        gW = whh + nt * 64 * 256 + kc * 64;
        gC = g_Gp[kc] + mt * 64 * 1024 + nt * 64;
    }

    // ---- one-time staging: per-batch data + invariant weights ----
    for (int i = tid * 4; i < 16384; i += NTHR * 4) {
        *(float4*)&sEnc[i] = *(const float4*)&enc[b * 16384 + i];
        *(float4*)&sP[i]   = *(const float4*)&g_P[b * 16384 + i];
    }
    sW2[tid] = w2[tid];
    for (int i = tid * 4; i < 4096; i += NTHR * 4)
        *(float4*)&sWih[i] = *(const float4*)&wih[i];
    {
        int i = tid * 4;
        float4 v1 = *(const float4*)&bih[i];
        float4 v2 = *(const float4*)&bhh[i];
        float4 o; o.x = v1.x + v2.x; o.y = v1.y + v2.y;
        o.z = v1.z + v2.z; o.w = v1.w + v2.w;
        *(float4*)&sBias[i] = o;
    }
    for (int i = tid; i < 1040; i += NTHR) sFcw[i] = fcw[i];
    sYh[tid] = yh[b * 256 + tid];
    if (tid == 0) sCst[0] = b2[0];
    if (tid < 4)  sCst[4 + tid] = fcb[tid];
    stageK(sW, 768, BwS, 32);
    stageK(gW, 256, BwG, 64);
    __syncthreads();

    // =======================================================================
    for (int t = 0; t < 64; t++) {
        const unsigned tgtPrev = (unsigned)(64 * t);         // h of step t
        const unsigned tgtCur  = (unsigned)(64 * (t + 1));

        // ---- phase A1: S task (K=32); needs h-half smt from step t-1 ------
        if (t > 0) flag_wait_ge(&g_cntH[smt], tgtPrev);
        {
            stageK(sA, 512, Ast, 32);
            __syncthreads();
            unsigned long long acc[4][2];
#pragma unroll
            for (int i = 0; i < 4; i++) { acc[i][0] = 0ull; acc[i][1] = 0ull; }
            mmaK(Ast, BwS, acc, 32);
            epilogue(acc, sC, 256, 0);
            __syncthreads();
            if (tid == 0) flag_arrive(&g_cntS[smt]);
        }

        // ---- phase A2: G task (K=64); needs h-half gmt (usually ready) ----
        if (t > 0 && gmt != smt) flag_wait_ge(&g_cntH[gmt], tgtPrev);
        {
            stageK(gA, 512, Ast, 64);
            __syncthreads();
            unsigned long long acc[4][2];
#pragma unroll
            for (int i = 0; i < 4; i++) { acc[i][0] = 0ull; acc[i][1] = 0ull; }
            mmaK(Ast, BwG, acc, 64);
            epilogue(acc, gC, 1024, 0);
            __syncthreads();
            if (tid == 0) flag_arrive(&g_cntG[gmt]);
        }

        // ---- phase B1: attention (needs S partials of my half only) -------
        flag_wait_ge(&g_cntS[bh], tgtCur);
        {
            float a0 = 0.f;
#pragma unroll
            for (int kc = 0; kc < 16; kc++) a0 += g_Sp[kc][b * 256 + tid];
            sS[tid] = a0;
        }
        __syncthreads();

        // scores + exp, sS/w2 register-cached
        {
            float sreg[8], wreg[8];
#pragma unroll
            for (int j = 0; j < 8; j++) {
                int e = lane + 32 * j;
                sreg[j] = sS[e];
                wreg[j] = sW2[e];
            }
            const float b2v = sCst[0];
            float wsum = 0.f;
            for (int ww = wid; ww < 64; ww += 8) {
                const float* Pp = &sP[ww * 256];
                float part = 0.f;
#pragma unroll
                for (int j = 0; j < 8; j++) {
                    int e = lane + 32 * j;
                    part += wreg[j] * tanh_fast(Pp[e] + sreg[j]);
                }
#pragma unroll
                for (int o = 16; o; o >>= 1) part += __shfl_xor_sync(0xffffffffu, part, o);
                float ev = __expf(part + b2v);
                if (lane == 0) { sAttn[ww] = ev; wsum += ev; }
            }
            if (lane == 0) sWsum[wid] = wsum;
        }
        __syncthreads();

        // context[e] = (1/Z) * sum_w attn[w] * enc[b,w,e]
        {
            float inv = 1.f / (sWsum[0] + sWsum[1] + sWsum[2] + sWsum[3]
                             + sWsum[4] + sWsum[5] + sWsum[6] + sWsum[7]);
            float acc = 0.f;
#pragma unroll 8
            for (int w = 0; w < 64; w++) acc += sAttn[w] * sEnc[w * 256 + tid];
            sCtx[tid] = acc * inv;
        }
        __syncthreads();

        // y_tilde (warps 0-3) || G-wait + g_Gp prefetch to smem (warps 4-7)
        if (wid < 4) {
            float acc = 0.f;
            const float* fr = &sFcw[wid * 260];
            for (int e = lane; e < 256; e += 32) acc += fr[e] * sCtx[e];
#pragma unroll
            for (int o = 16; o; o >>= 1) acc += __shfl_xor_sync(0xffffffffu, acc, o);
            if (lane == 0) {
                float yv = 0.f;
#pragma unroll
                for (int f = 0; f < 4; f++) yv += fr[256 + f] * sYh[t * 4 + f];
                sY[wid] = acc + yv + sCst[4 + wid];
            }
        } else {
            if (wid == 4 && lane == 0) flag_poll_ge(&g_cntG[bh], tgtCur);
            asm volatile("bar.sync 1, 128;" ::: "memory");   // warps 4-7 only
            int i = (tid - 128) * 8;                         // 128 thr x 8 = 1024
            float4 o0 = make_float4(0.f, 0.f, 0.f, 0.f);
            float4 o1 = make_float4(0.f, 0.f, 0.f, 0.f);
#pragma unroll
            for (int kc = 0; kc < 4; kc++) {
                float4 a0 = *(const float4*)&g_Gp[kc][b * 1024 + i];
                float4 a1 = *(const float4*)&g_Gp[kc][b * 1024 + i + 4];
                o0.x += a0.x; o0.y += a0.y; o0.z += a0.z; o0.w += a0.w;
                o1.x += a1.x; o1.y += a1.y; o1.z += a1.z; o1.w += a1.w;
            }
            *(float4*)&sGG[i]     = o0;
            *(float4*)&sGG[i + 4] = o1;
        }
        __syncthreads();

        // ---- phase B2: gates + LSTM cell (all smem, HW transcendentals) ---
        // WAR-safe: cntS[bh]/cntG[bh] >= 64(t+1) imply every reader of
        // g_HC half bh has finished staging step t's operands.
        {
            int j = tid;
            float g[4];
#pragma unroll
            for (int q = 0; q < 4; q++) {
                int d = q * 256 + j;
                float4 wr = *(const float4*)&sWih[d * 4];
                g[q] = sGG[d] + sBias[d]
                     + wr.x * sY[0] + wr.y * sY[1] + wr.z * sY[2] + wr.w * sY[3];
            }
            float ig = sigmoid_fast(g[0]);
            float fg = sigmoid_fast(g[1]);
            float gg = tanh_fast(g[2]);
            float og = sigmoid_fast(g[3]);
            float c_old = g_HC[b * 512 + 256 + j];
            float c_new = fg * c_old + ig * gg;
            float h_new = og * tanh_fast(c_new);
            g_HC[b * 512 + j]       = h_new;
            g_HC[b * 512 + 256 + j] = c_new;
            if (t == 63) sH[j] = h_new;
        }

        // final output at last step: out[b,:] = fcf([h, ctx])
        if (t == 63) {
            __syncthreads();
            if (wid < 4) {
                float acc = 0.f;
                const float* fr = &fcfw[wid * 512];
                for (int i = lane; i < 512; i += 32) {
                    float v = (i < 256) ? sH[i] : sCtx[i - 256];
                    acc += fr[i] * v;
                }
#pragma unroll
                for (int o = 16; o; o >>= 1) acc += __shfl_xor_sync(0xffffffffu, acc, o);
                if (lane == 0) out[b * 4 + wid] = acc + fcfb[wid];
            }
        }

        // ---- publish my h,c for the next step (no wait here) --------------
        __syncthreads();
        if (tid == 0) flag_arrive(&g_cntH[bh]);
    }

    // full two-hop barrier once, then reset monotonic counters (replay-safe)
    grid_barrier();
    if (b == 0 && tid == 0) {
        asm volatile("st.relaxed.gpu.global.u32 [%0], %1;" :: "l"(&g_cntP), "r"(0u));
        asm volatile("st.relaxed.gpu.global.u32 [%0], %1;" :: "l"(&g_cntS[0]), "r"(0u));
        asm volatile("st.relaxed.gpu.global.u32 [%0], %1;" :: "l"(&g_cntS[1]), "r"(0u));
        asm volatile("st.relaxed.gpu.global.u32 [%0], %1;" :: "l"(&g_cntG[0]), "r"(0u));
        asm volatile("st.relaxed.gpu.global.u32 [%0], %1;" :: "l"(&g_cntG[1]), "r"(0u));
        asm volatile("st.relaxed.gpu.global.u32 [%0], %1;" :: "l"(&g_cntH[0]), "r"(0u));
        asm volatile("st.relaxed.gpu.global.u32 [%0], %1;" :: "l"(&g_cntH[1]), "r"(0u));
    }
}

// ---------------------------------------------------------------------------
extern "C" void kernel_launch(void* const* d_in, const int* in_sizes, int n_in,
                              void* d_out, int out_size) {
    const float* enc  = (const float*)d_in[0];
    const float* yh   = (const float*)d_in[1];
    const float* w1   = (const float*)d_in[2];
    const float* b1   = (const float*)d_in[3];
    const float* w2   = (const float*)d_in[4];
    const float* b2   = (const float*)d_in[5];
    const float* wih  = (const float*)d_in[6];
    const float* whh  = (const float*)d_in[7];
    const float* bih  = (const float*)d_in[8];
    const float* bhh  = (const float*)d_in[9];
    const float* fcw  = (const float*)d_in[10];
    const float* fcb  = (const float*)d_in[11];
    const float* fcfw = (const float*)d_in[12];
    const float* fcfb = (const float*)d_in[13];
    float* out = (float*)d_out;

    static int configured = 0;
    if (!configured) {
        cudaFuncSetAttribute(decoder_persistent,
                             cudaFuncAttributeMaxDynamicSharedMemorySize, SMEM_BYTES);
        configured = 1;
    }
    decoder_persistent<<<NBLK, NTHR, SMEM_BYTES>>>(
        enc, yh, w1, b1, w2, b2, wih, whh, bih, bhh, fcw, fcb, fcfw, fcfb, out);
}

// round 16
// speedup vs baseline: 1.0613x; 1.0613x over previous
#include <cuda_runtime.h>
#include <stdint.h>
#include <math.h>

#define NBLK 128
#define NTHR 256

// __device__ scratch (allocation-free rule)
__device__ float g_P[128 * 64 * 256];        // P[b,w,e] (8 MB)
__device__ float g_HC[128 * 512];            // [b][0:256]=h, [b][256:512]=c
__device__ float g_Sp[16][128 * 256];        // S kc-partials (K=32 each)
__device__ float g_Gp[4][128 * 1024];        // Ghh kc-partials (K=64 each)
__device__ unsigned g_cntP, g_cntS, g_cntG, g_cntH;   // monotonic flags
__device__ unsigned g_bar_gen, g_bar_cnt;             // final barrier only

// ---- smem float offsets (total 55840 floats = 223360 B) ----
#define F_ENC   0        // 16384
#define F_P     16384    // 16384
#define F_W2    32768    // 256
#define F_WIH   33024    // 4096
#define F_BIAS  37120    // 1024 (bih+bhh)
#define F_FCW   38144    // 1048 (fcw 1040, pad)
#define F_YH    39192    // 256  (yh[b] all steps)
#define F_CONST 39448    // 8    ([0]=b2, [4..7]=fcb)
#define F_SCR   39456    // 16384: init Ast|Bst; steady layout below
#define SMEM_BYTES (55840 * 4)

// steady-state scratch sublayout (floats, relative to F_SCR)
#define SC_ASTS 0        // 2048 (S A-tile, K=32; phase-B overlay also here)
#define SC_BWS  4096     // 2048 (persistent S weight tile 64x32)
#define SC_BWG  6144     // 4096 (persistent G weight tile 64x64)
#define SC_ASTG 10240    // 4096 (G A-tile, K=64)

// ---------------------------------------------------------------------------
__device__ __forceinline__ float tanh_fast(float x) {
    float y;
    asm("tanh.approx.f32 %0, %1;" : "=f"(y) : "f"(x));
    return y;
}
__device__ __forceinline__ float sigmoid_fast(float x) {
    return fmaf(tanh_fast(0.5f * x), 0.5f, 0.5f);
}
__device__ __forceinline__ unsigned long long pack2(float x, float y) {
    unsigned long long r;
    asm("mov.b64 %0, {%1, %2};" : "=l"(r) : "f"(x), "f"(y));
    return r;
}
__device__ __forceinline__ unsigned long long fma2(unsigned long long a,
                                                   unsigned long long b,
                                                   unsigned long long c) {
    unsigned long long d;
    asm("fma.rn.f32x2 %0, %1, %2, %3;" : "=l"(d) : "l"(a), "l"(b), "l"(c));
    return d;
}
__device__ __forceinline__ float2 unpack2(unsigned long long v) {
    float lo, hi;
    asm("mov.b64 {%0, %1}, %2;" : "=f"(lo), "=f"(hi) : "l"(v));
    return make_float2(lo, hi);
}

// fire-and-forget arrival (tid0, after __syncthreads)
__device__ __forceinline__ void flag_arrive(unsigned* p) {
    asm volatile("red.release.gpu.global.add.u32 [%0], %1;" :: "l"(p), "r"(1u));
}
__device__ __forceinline__ void flag_poll_ge(unsigned* p, unsigned target) {
    unsigned v;
    do {
        asm volatile("ld.acquire.gpu.global.u32 %0, [%1];" : "=r"(v) : "l"(p));
    } while (v < target);
}
__device__ __forceinline__ void flag_wait_ge(unsigned* p, unsigned target) {
    if (threadIdx.x == 0) flag_poll_ge(p, target);
    __syncthreads();
}

// two-hop barrier, used ONCE after the loop (reset safety)
__device__ __forceinline__ void grid_barrier() {
    __syncthreads();
    if (threadIdx.x == 0) {
        unsigned gen;
        asm volatile("ld.acquire.gpu.global.u32 %0, [%1];" : "=r"(gen) : "l"(&g_bar_gen));
        if (blockIdx.x == 0) {
            unsigned c;
            do {
                asm volatile("ld.acquire.gpu.global.u32 %0, [%1];" : "=r"(c) : "l"(&g_bar_cnt));
            } while (c != NBLK - 1);
            asm volatile("st.relaxed.gpu.global.u32 [%0], %1;" :: "l"(&g_bar_cnt), "r"(0u));
            asm volatile("st.release.gpu.global.u32 [%0], %1;" :: "l"(&g_bar_gen), "r"(gen + 1u));
        } else {
            asm volatile("red.release.gpu.global.add.u32 [%0], %1;" :: "l"(&g_bar_cnt), "r"(1u));
            unsigned g2;
            do {
                asm volatile("ld.acquire.gpu.global.u32 %0, [%1];" : "=r"(g2) : "l"(&g_bar_gen));
            } while (g2 == gen);
        }
    }
    __syncthreads();
}

// ---------------------------------------------------------------------------
// Stage 64 rows x K cols of X (row-major ldx) into Xst[k][r] (stride 64).
__device__ __forceinline__ void stageK(const float* __restrict__ Xp, int ldx,
                                       float* __restrict__ Xst, int K) {
    const int tid = threadIdx.x;
    const int r  = tid & 63;
    const int kg = tid >> 6;
    const int nq = K >> 4;
#pragma unroll
    for (int q = 0; q < nq; q++) {
        int k4 = (kg + q * 4) << 2;
        float4 v = *(const float4*)(Xp + r * ldx + k4);
        Xst[(k4 + 0) * 64 + r] = v.x;
        Xst[(k4 + 1) * 64 + r] = v.y;
        Xst[(k4 + 2) * 64 + r] = v.z;
        Xst[(k4 + 3) * 64 + r] = v.w;
    }
}

// 64x64 x K accumulate with packed f32x2 FMA. acc[4][2] packed pairs.
__device__ __forceinline__ void mmaK(const float* __restrict__ Ast,
                                     const float* __restrict__ Bst,
                                     unsigned long long acc[4][2], int K) {
    const int ty = threadIdx.x >> 4, tx = threadIdx.x & 15;
#pragma unroll 8
    for (int k = 0; k < K; k++) {
        float4 a = *(const float4*)&Ast[k * 64 + ty * 4];
        ulonglong2 b = *(const ulonglong2*)&Bst[k * 64 + tx * 4];
        unsigned long long a0 = pack2(a.x, a.x);
        unsigned long long a1 = pack2(a.y, a.y);
        unsigned long long a2 = pack2(a.z, a.z);
        unsigned long long a3 = pack2(a.w, a.w);
        acc[0][0] = fma2(a0, b.x, acc[0][0]); acc[0][1] = fma2(a0, b.y, acc[0][1]);
        acc[1][0] = fma2(a1, b.x, acc[1][0]); acc[1][1] = fma2(a1, b.y, acc[1][1]);
        acc[2][0] = fma2(a2, b.x, acc[2][0]); acc[2][1] = fma2(a2, b.y, acc[2][1]);
        acc[3][0] = fma2(a3, b.x, acc[3][0]); acc[3][1] = fma2(a3, b.y, acc[3][1]);
    }
}

__device__ __forceinline__ void epilogue(unsigned long long acc[4][2],
                                         float* __restrict__ Cptr, int ldc,
                                         const float* __restrict__ bias) {
    const int ty = threadIdx.x >> 4, tx = threadIdx.x & 15;
    float4 bb = make_float4(0.f, 0.f, 0.f, 0.f);
    if (bias) bb = *(const float4*)&bias[tx * 4];
#pragma unroll
    for (int i = 0; i < 4; i++) {
        float2 lo = unpack2(acc[i][0]);
        float2 hi = unpack2(acc[i][1]);
        float4 o;
        o.x = lo.x + bb.x; o.y = lo.y + bb.y;
        o.z = hi.x + bb.z; o.w = hi.y + bb.w;
        *(float4*)&Cptr[(ty * 4 + i) * ldc + tx * 4] = o;
    }
}

// Full tile GEMM (stages both operands) for the one-time P precompute.
__device__ __forceinline__ void gemm64_full(
    const float* __restrict__ Aptr, int lda,
    const float* __restrict__ Bptr, int ldb,
    float* __restrict__ Cptr, int ldc,
    int nchunk, const float* __restrict__ bias,
    float* __restrict__ Ast, float* __restrict__ Bst)
{
    unsigned long long acc[4][2];
#pragma unroll
    for (int i = 0; i < 4; i++) { acc[i][0] = 0ull; acc[i][1] = 0ull; }
    for (int c = 0; c < nchunk; c++) {
        stageK(Aptr + c * 128, lda, Ast, 128);
        stageK(Bptr + c * 128, ldb, Bst, 128);
        __syncthreads();
        mmaK(Ast, Bst, acc, 128);
        __syncthreads();
    }
    epilogue(acc, Cptr, ldc, bias);
}

// ---------------------------------------------------------------------------
__global__ __launch_bounds__(NTHR, 1)
void decoder_persistent(
    const float* __restrict__ enc,  const float* __restrict__ yh,
    const float* __restrict__ w1,   const float* __restrict__ b1,
    const float* __restrict__ w2,   const float* __restrict__ b2,
    const float* __restrict__ wih,  const float* __restrict__ whh,
    const float* __restrict__ bih,  const float* __restrict__ bhh,
    const float* __restrict__ fcw,  const float* __restrict__ fcb,
    const float* __restrict__ fcfw, const float* __restrict__ fcfb,
    float* __restrict__ out)
{
    extern __shared__ float sm[];
    float* sEnc  = sm + F_ENC;
    float* sP    = sm + F_P;
    float* sW2   = sm + F_W2;
    float* sWih  = sm + F_WIH;
    float* sBias = sm + F_BIAS;
    float* sFcw  = sm + F_FCW;
    float* sYh   = sm + F_YH;
    float* sCst  = sm + F_CONST;
    float* scr   = sm + F_SCR;
    float* AstS  = scr + SC_ASTS;  // 2048 floats (K=32)
    float* BwS   = scr + SC_BWS;   // persistent S weight tile (64x32)
    float* BwG   = scr + SC_BWG;   // persistent G weight tile (64x64)
    float* AstG  = scr + SC_ASTG;  // 4096 floats (K=64)
    // phase-B overlay (inside AstS region and beyond; BwS/BwG/AstG safe zones:
    // overlay uses scr[0..2047]; sGG at scr+1024 overlaps AstS tail only)
    float* sS    = scr;
    float* sCtx  = scr + 256;
    float* sAttn = scr + 576;
    float* sWsum = scr + 640;
    float* sY    = scr + 656;
    float* sH    = scr + 672;      // 672..927
    float* sGG   = scr + 1024;     // 1024..2047 (gate partial sums)

    const int b   = blockIdx.x;
    const int tid = threadIdx.x;
    const int lane = tid & 31, wid = tid >> 5;

    // ---- init: zero h,c for my batch ----
    g_HC[b * 512 + tid]       = 0.f;
    g_HC[b * 512 + 256 + tid] = 0.f;

    // ---- precompute P = enc · W1_e^T + b1 : 512 tiles of 64x64x256 ----
    // (init uses scr[0..16383] as Ast|Bst; persistent tiles staged after)
    for (int q = 0; q < 4; q++) {
        int tile = b + NBLK * q;           // mt 0..127, nt 0..3
        int mt = tile >> 2, nt = tile & 3;
        gemm64_full(enc + mt * 64 * 256, 256,
                    w1 + nt * 64 * 768 + 512, 768,
                    g_P + mt * 64 * 256 + nt * 64, 256,
                    2, b1 + nt * 64, scr, scr + 8192);
    }
    __syncthreads();
    if (tid == 0) flag_arrive(&g_cntP);
    flag_wait_ge(&g_cntP, NBLK);

    // ---- decode my two fixed per-step GEMM tasks ----
    // S: b = kc*8 + mt*4 + nt  (kc 0..15, mt 0..1, nt 0..3), K=32
    // G: b = kc*32 + mt*16 + nt (kc 0..3, mt 0..1, nt 0..15), K=64
    const float *sA, *sW, *gA, *gW;
    float *sC, *gC;
    {
        int kc = b >> 3, mt = (b >> 2) & 1, nt = b & 3;
        sA = g_HC + mt * 64 * 512 + kc * 32;
        sW = w1 + nt * 64 * 768 + kc * 32;
        sC = g_Sp[kc] + mt * 64 * 256 + nt * 64;
    }
    {
        int kc = b >> 5, mt = (b >> 4) & 1, nt = b & 15;
        gA = g_HC + mt * 64 * 512 + kc * 64;
        gW = whh + nt * 64 * 256 + kc * 64;
        gC = g_Gp[kc] + mt * 64 * 1024 + nt * 64;
    }

    // ---- one-time staging: per-batch data + invariant weights ----
    for (int i = tid * 4; i < 16384; i += NTHR * 4) {
        *(float4*)&sEnc[i] = *(const float4*)&enc[b * 16384 + i];
        *(float4*)&sP[i]   = *(const float4*)&g_P[b * 16384 + i];
    }
    sW2[tid] = w2[tid];
    for (int i = tid * 4; i < 4096; i += NTHR * 4)
        *(float4*)&sWih[i] = *(const float4*)&wih[i];
    {
        int i = tid * 4;
        float4 v1 = *(const float4*)&bih[i];
        float4 v2 = *(const float4*)&bhh[i];
        float4 o; o.x = v1.x + v2.x; o.y = v1.y + v2.y;
        o.z = v1.z + v2.z; o.w = v1.w + v2.w;
        *(float4*)&sBias[i] = o;
    }
    for (int i = tid; i < 1040; i += NTHR) sFcw[i] = fcw[i];
    sYh[tid] = yh[b * 256 + tid];
    if (tid == 0) sCst[0] = b2[0];
    if (tid < 4)  sCst[4 + tid] = fcb[tid];
    stageK(sW, 768, BwS, 32);
    stageK(gW, 256, BwG, 64);
    __syncthreads();

    // =======================================================================
    for (int t = 0; t < 64; t++) {
        const unsigned tgt = (unsigned)(128 * (t + 1));

        // ---- phase A: stage BOTH A-operands (one LDG latency), then S, G --
        {
            stageK(sA, 512, AstS, 32);     // LDGs for S and G issue together
            stageK(gA, 512, AstG, 64);
            __syncthreads();

            unsigned long long acc[4][2];
#pragma unroll
            for (int i = 0; i < 4; i++) { acc[i][0] = 0ull; acc[i][1] = 0ull; }
            mmaK(AstS, BwS, acc, 32);      // S task (K=32)
            epilogue(acc, sC, 256, 0);
            __syncthreads();
            if (tid == 0) flag_arrive(&g_cntS);

#pragma unroll
            for (int i = 0; i < 4; i++) { acc[i][0] = 0ull; acc[i][1] = 0ull; }
            mmaK(AstG, BwG, acc, 64);      // G task (K=64), no re-stage
            epilogue(acc, gC, 1024, 0);
            __syncthreads();
            if (tid == 0) flag_arrive(&g_cntG);
        }

        // ---- phase B1: attention (needs all S) ----------------------------
        flag_wait_ge(&g_cntS, tgt);
        {
            float a0 = 0.f;
#pragma unroll
            for (int kc = 0; kc < 16; kc++) a0 += g_Sp[kc][b * 256 + tid];
            sS[tid] = a0;
        }
        __syncthreads();

        // scores + exp, sS/w2 register-cached
        {
            float sreg[8], wreg[8];
#pragma unroll
            for (int j = 0; j < 8; j++) {
                int e = lane + 32 * j;
                sreg[j] = sS[e];
                wreg[j] = sW2[e];
            }
            const float b2v = sCst[0];
            float wsum = 0.f;
            for (int ww = wid; ww < 64; ww += 8) {
                const float* Pp = &sP[ww * 256];
                float part = 0.f;
#pragma unroll
                for (int j = 0; j < 8; j++) {
                    int e = lane + 32 * j;
                    part += wreg[j] * tanh_fast(Pp[e] + sreg[j]);
                }
#pragma unroll
                for (int o = 16; o; o >>= 1) part += __shfl_xor_sync(0xffffffffu, part, o);
                float ev = __expf(part + b2v);
                if (lane == 0) { sAttn[ww] = ev; wsum += ev; }
            }
            if (lane == 0) sWsum[wid] = wsum;
        }
        __syncthreads();

        // context[e] = (1/Z) * sum_w attn[w] * enc[b,w,e]
        {
            float inv = 1.f / (sWsum[0] + sWsum[1] + sWsum[2] + sWsum[3]
                             + sWsum[4] + sWsum[5] + sWsum[6] + sWsum[7]);
            float acc = 0.f;
#pragma unroll 8
            for (int w = 0; w < 64; w++) acc += sAttn[w] * sEnc[w * 256 + tid];
            sCtx[tid] = acc * inv;
        }
        __syncthreads();

        // y_tilde (warps 0-3) || G-wait + g_Gp prefetch to smem (warps 4-7)
        if (wid < 4) {
            float acc = 0.f;
            const float* fr = &sFcw[wid * 260];
            for (int e = lane; e < 256; e += 32) acc += fr[e] * sCtx[e];
#pragma unroll
            for (int o = 16; o; o >>= 1) acc += __shfl_xor_sync(0xffffffffu, acc, o);
            if (lane == 0) {
                float yv = 0.f;
#pragma unroll
                for (int f = 0; f < 4; f++) yv += fr[256 + f] * sYh[t * 4 + f];
                sY[wid] = acc + yv + sCst[4 + wid];
            }
        } else {
            if (wid == 4 && lane == 0) flag_poll_ge(&g_cntG, tgt);
            asm volatile("bar.sync 1, 128;" ::: "memory");   // warps 4-7 only
            int i = (tid - 128) * 8;                         // 128 thr x 8 = 1024
            float4 o0 = make_float4(0.f, 0.f, 0.f, 0.f);
            float4 o1 = make_float4(0.f, 0.f, 0.f, 0.f);
#pragma unroll
            for (int kc = 0; kc < 4; kc++) {
                float4 a0 = *(const float4*)&g_Gp[kc][b * 1024 + i];
                float4 a1 = *(const float4*)&g_Gp[kc][b * 1024 + i + 4];
                o0.x += a0.x; o0.y += a0.y; o0.z += a0.z; o0.w += a0.w;
                o1.x += a1.x; o1.y += a1.y; o1.z += a1.z; o1.w += a1.w;
            }
            *(float4*)&sGG[i]     = o0;
            *(float4*)&sGG[i + 4] = o1;
        }
        __syncthreads();

        // ---- phase B2: gates + LSTM cell (all smem, HW transcendentals) ---
        {
            int j = tid;
            float g[4];
#pragma unroll
            for (int q = 0; q < 4; q++) {
                int d = q * 256 + j;
                float4 wr = *(const float4*)&sWih[d * 4];
                g[q] = sGG[d] + sBias[d]
                     + wr.x * sY[0] + wr.y * sY[1] + wr.z * sY[2] + wr.w * sY[3];
            }
            float ig = sigmoid_fast(g[0]);
            float fg = sigmoid_fast(g[1]);
            float gg = tanh_fast(g[2]);
            float og = sigmoid_fast(g[3]);
            float c_old = g_HC[b * 512 + 256 + j];
            float c_new = fg * c_old + ig * gg;
            float h_new = og * tanh_fast(c_new);
            g_HC[b * 512 + j]       = h_new;
            g_HC[b * 512 + 256 + j] = c_new;
            if (t == 63) sH[j] = h_new;
        }

        // final output at last step: out[b,:] = fcf([h, ctx])
        if (t == 63) {
            __syncthreads();
            if (wid < 4) {
                float acc = 0.f;
                const float* fr = &fcfw[wid * 512];
                for (int i = lane; i < 512; i += 32) {
                    float v = (i < 256) ? sH[i] : sCtx[i - 256];
                    acc += fr[i] * v;
                }
#pragma unroll
                for (int o = 16; o; o >>= 1) acc += __shfl_xor_sync(0xffffffffu, acc, o);
                if (lane == 0) out[b * 4 + wid] = acc + fcfb[wid];
            }
        }

        // ---- end-of-step: one-hop full sync on h,c ------------------------
        __syncthreads();
        if (tid == 0) flag_arrive(&g_cntH);
        flag_wait_ge(&g_cntH, tgt);
    }

    // full two-hop barrier once, then reset monotonic counters (replay-safe)
    grid_barrier();
    if (b == 0 && tid == 0) {
        asm volatile("st.relaxed.gpu.global.u32 [%0], %1;" :: "l"(&g_cntP), "r"(0u));
        asm volatile("st.relaxed.gpu.global.u32 [%0], %1;" :: "l"(&g_cntS), "r"(0u));
        asm volatile("st.relaxed.gpu.global.u32 [%0], %1;" :: "l"(&g_cntG), "r"(0u));
        asm volatile("st.relaxed.gpu.global.u32 [%0], %1;" :: "l"(&g_cntH), "r"(0u));
    }
}

// ---------------------------------------------------------------------------
extern "C" void kernel_launch(void* const* d_in, const int* in_sizes, int n_in,
                              void* d_out, int out_size) {
    const float* enc  = (const float*)d_in[0];
    const float* yh   = (const float*)d_in[1];
    const float* w1   = (const float*)d_in[2];
    const float* b1   = (const float*)d_in[3];
    const float* w2   = (const float*)d_in[4];
    const float* b2   = (const float*)d_in[5];
    const float* wih  = (const float*)d_in[6];
    const float* whh  = (const float*)d_in[7];
    const float* bih  = (const float*)d_in[8];
    const float* bhh  = (const float*)d_in[9];
    const float* fcw  = (const float*)d_in[10];
    const float* fcb  = (const float*)d_in[11];
    const float* fcfw = (const float*)d_in[12];
    const float* fcfb = (const float*)d_in[13];
    float* out = (float*)d_out;

    static int configured = 0;
    if (!configured) {
        cudaFuncSetAttribute(decoder_persistent,
                             cudaFuncAttributeMaxDynamicSharedMemorySize, SMEM_BYTES);
        configured = 1;
    }
    decoder_persistent<<<NBLK, NTHR, SMEM_BYTES>>>(
        enc, yh, w1, b1, w2, b2, wih, whh, bih, bhh, fcw, fcb, fcfw, fcfb, out);
}